// round 15
// baseline (speedup 1.0000x reference)
#include <cuda_runtime.h>
#include <cuda_fp16.h>
#include <math.h>
#include <stdint.h>

#define BB 2
#define SS 2048
#define DD 1024
#define HH 16
#define DK 64
#define MTOT (BB*SS)

#define SCALE 12.5f                  // 100/sqrt(64)
#define INV_HS (1.0f/32768.0f)       // 1/(H*S)

// ---------------- device scratch ----------------------------------------------
__device__ __half g_inH[16777216];
__device__ __half g_inL[16777216];
__device__ __half g_QH[4194304], g_QL[4194304];
__device__ __half g_KH[4194304], g_KL[4194304];
__device__ __half g_VtH[4194304];                   // [b*1024+n][2048] transposed
__device__ __half g_CH[4194304];                    // C stored hi-only (O-GEMM 2-term)
// u scratch, uint4-chunked: chunk c of (blk,tile) at ((blk*32+tile)*4 + c)*256 + t
__device__ uint32_t g_U[512ull * 32 * 16 * 256];
__device__ int g_ctr;                               // persistent-attention work counter

// ---------------- helpers -----------------------------------------------------
__device__ __forceinline__ void split_h2(float a, float b, __half2& h, __half2& l) {
    h = __floats2half2_rn(a, b);
    float2 f = __half22float2(h);
    l = __floats2half2_rn(a - f.x, b - f.y);
}

__device__ __forceinline__ void mma_f16(float c[4],
                                        uint32_t a0, uint32_t a1, uint32_t a2, uint32_t a3,
                                        uint32_t b0, uint32_t b1) {
    asm volatile(
        "mma.sync.aligned.m16n8k16.row.col.f32.f16.f16.f32 "
        "{%0,%1,%2,%3}, {%4,%5,%6,%7}, {%8,%9}, {%0,%1,%2,%3};"
        : "+f"(c[0]), "+f"(c[1]), "+f"(c[2]), "+f"(c[3])
        : "r"(a0), "r"(a1), "r"(a2), "r"(a3), "r"(b0), "r"(b1));
}

__device__ __forceinline__ void ldsm_x4(uint32_t& r0, uint32_t& r1,
                                        uint32_t& r2, uint32_t& r3, uint32_t addr) {
    asm volatile("ldmatrix.sync.aligned.m8n8.x4.shared.b16 {%0,%1,%2,%3}, [%4];"
        : "=r"(r0), "=r"(r1), "=r"(r2), "=r"(r3) : "r"(addr));
}

__device__ __forceinline__ uint32_t smem_u32(const void* p) {
    uint32_t a;
    asm("{ .reg .u64 t; cvta.to.shared.u64 t, %1; cvt.u32.u64 %0, t; }"
        : "=r"(a) : "l"(p));
    return a;
}

#define CP_ASYNC16(dst, src) \
    asm volatile("cp.async.cg.shared.global [%0], [%1], 16;" :: "r"(dst), "l"(src))
#define CP_COMMIT() asm volatile("cp.async.commit_group;" ::: "memory")
#define CP_WAIT0()  asm volatile("cp.async.wait_group 0;" ::: "memory")

// ---------------- zero mean_atp + reset work counter ---------------------------
__global__ void zero_atp_kernel(float* __restrict__ atp) {
    int i = blockIdx.x * blockDim.x + threadIdx.x;
    if (i < BB*SS) atp[i] = 0.0f;
    if (i == 0) g_ctr = 0;
}

// ---------------- pre-split fp32 -> hi/lo fp16 --------------------------------
__global__ void split_kernel(const float* __restrict__ src,
                             __half* __restrict__ H, __half* __restrict__ L,
                             int n4) {
    int i = blockIdx.x * blockDim.x + threadIdx.x;
    if (i < n4) {
        float4 v = ((const float4*)src)[i];
        __half2 h01, l01, h23, l23;
        split_h2(v.x, v.y, h01, l01);
        split_h2(v.z, v.w, h23, l23);
        ((__half2*)H)[2*i]   = h01;
        ((__half2*)H)[2*i+1] = h23;
        ((__half2*)L)[2*i]   = l01;
        ((__half2*)L)[2*i+1] = l23;
    }
}

// ---------------- templated fp16 GEMM (3-term or 2-term) ----------------------
#define GK 1024
#define GN 1024
#define LDH 40
#define MAT_B 10240
#define BUF_B 40960
#define GEMM_SMEM 81920
#define EP_H16 0
#define EP_VT 1
#define EP_F32 2

template<int NT>
__global__ __launch_bounds__(256, 2) void gemm_h16(
    const __half* __restrict__ XH, const __half* __restrict__ XL,
    const __half* __restrict__ WH, const __half* __restrict__ WL,
    const float* __restrict__ bias, int mode,
    __half* __restrict__ YH, __half* __restrict__ YL, float* __restrict__ YF)
{
    extern __shared__ char sm[];
    const uint32_t smb = smem_u32(sm);

    const int t = threadIdx.x;
    const int w = t >> 5;
    const int lane = t & 31;
    const int g = lane >> 2;
    const int tig = lane & 3;
    const int warp_m = (w >> 2) * 64;
    const int warp_n = (w & 3) * 32;
    const int bm = blockIdx.y * 128;
    const int bn = blockIdx.x * 128;

    const int arow = lane & 15;
    const int acol = (lane >> 4) * 8;
    const int brow = (lane & 7) + ((lane >> 4) << 3);
    const int bcol = ((lane >> 3) & 1) * 8;

    const int r0c = t >> 2, c0c = t & 3;
    const int r1c = (t + 256) >> 2;

    float acc[4][4][4];
#pragma unroll
    for (int mi = 0; mi < 4; ++mi)
#pragma unroll
        for (int ni = 0; ni < 4; ++ni)
#pragma unroll
            for (int j = 0; j < 4; ++j) acc[mi][ni][j] = 0.0f;

    const int NS = GK / 32;

    auto issue = [&](int s, int buf) {
        const uint32_t bb = smb + buf * BUF_B;
        const size_t ks = (size_t)s * 32;
        CP_ASYNC16(bb + r0c * 80 + c0c * 16, XH + (size_t)(bm + r0c) * GK + ks + c0c * 8);
        CP_ASYNC16(bb + r1c * 80 + c0c * 16, XH + (size_t)(bm + r1c) * GK + ks + c0c * 8);
        if (NT == 3) {
            CP_ASYNC16(bb + MAT_B + r0c * 80 + c0c * 16, XL + (size_t)(bm + r0c) * GK + ks + c0c * 8);
            CP_ASYNC16(bb + MAT_B + r1c * 80 + c0c * 16, XL + (size_t)(bm + r1c) * GK + ks + c0c * 8);
        }
        CP_ASYNC16(bb + 2 * MAT_B + r0c * 80 + c0c * 16, WH + (size_t)(bn + r0c) * GK + ks + c0c * 8);
        CP_ASYNC16(bb + 2 * MAT_B + r1c * 80 + c0c * 16, WH + (size_t)(bn + r1c) * GK + ks + c0c * 8);
        CP_ASYNC16(bb + 3 * MAT_B + r0c * 80 + c0c * 16, WL + (size_t)(bn + r0c) * GK + ks + c0c * 8);
        CP_ASYNC16(bb + 3 * MAT_B + r1c * 80 + c0c * 16, WL + (size_t)(bn + r1c) * GK + ks + c0c * 8);
    };

    issue(0, 0);
    CP_COMMIT();

    for (int s = 0; s < NS; ++s) {
        const int buf = s & 1;
        CP_WAIT0();
        __syncthreads();
        if (s + 1 < NS) {
            issue(s + 1, buf ^ 1);
            CP_COMMIT();
        }

        const uint32_t xb = smb + buf * BUF_B;
        const uint32_t wb = xb + 2 * MAT_B;

#pragma unroll
        for (int k16 = 0; k16 < 2; ++k16) {
            const int k0 = k16 * 16;
            uint32_t bh[4][2], bl[4][2];
#pragma unroll
            for (int p = 0; p < 2; ++p) {
                const uint32_t addr = wb + ((warp_n + p * 16 + brow) * LDH + k0 + bcol) * 2;
                ldsm_x4(bh[2*p][0], bh[2*p][1], bh[2*p+1][0], bh[2*p+1][1], addr);
                ldsm_x4(bl[2*p][0], bl[2*p][1], bl[2*p+1][0], bl[2*p+1][1], addr + MAT_B);
            }
#pragma unroll
            for (int mi = 0; mi < 4; ++mi) {
                const uint32_t addrA = xb + ((warp_m + mi * 16 + arow) * LDH + k0 + acol) * 2;
                uint32_t ah[4], al[4];
                ldsm_x4(ah[0], ah[1], ah[2], ah[3], addrA);
                if (NT == 3)
                    ldsm_x4(al[0], al[1], al[2], al[3], addrA + MAT_B);
#pragma unroll
                for (int ni = 0; ni < 4; ++ni) {
                    mma_f16(acc[mi][ni], ah[0], ah[1], ah[2], ah[3], bh[ni][0], bh[ni][1]);
                    mma_f16(acc[mi][ni], ah[0], ah[1], ah[2], ah[3], bl[ni][0], bl[ni][1]);
                    if (NT == 3)
                        mma_f16(acc[mi][ni], al[0], al[1], al[2], al[3], bh[ni][0], bh[ni][1]);
                }
            }
        }
        __syncthreads();
    }

    // ---- epilogue ----
#pragma unroll
    for (int ni = 0; ni < 4; ++ni) {
        const int n = bn + warp_n + ni * 8 + 2 * tig;
        const float2 b2 = *(const float2*)(bias + n);
#pragma unroll
        for (int mi = 0; mi < 4; ++mi) {
            const int r0 = bm + warp_m + mi * 16;
            float c0 = acc[mi][ni][0] + b2.x, c1 = acc[mi][ni][1] + b2.y;
            float c2 = acc[mi][ni][2] + b2.x, c3 = acc[mi][ni][3] + b2.y;
            if (mode == EP_F32) {
                *(float2*)(YF + (size_t)(r0 + g) * GN + n)     = make_float2(c0, c1);
                *(float2*)(YF + (size_t)(r0 + g + 8) * GN + n) = make_float2(c2, c3);
            } else if (mode == EP_H16) {
                __half2 h01, l01, h23, l23;
                split_h2(c0, c1, h01, l01);
                split_h2(c2, c3, h23, l23);
                *(__half2*)(YH + (size_t)(r0 + g) * GN + n)     = h01;
                *(__half2*)(YL + (size_t)(r0 + g) * GN + n)     = l01;
                *(__half2*)(YH + (size_t)(r0 + g + 8) * GN + n) = h23;
                *(__half2*)(YL + (size_t)(r0 + g + 8) * GN + n) = l23;
            } else {   // EP_VT: hi only
                __half2 h01 = __floats2half2_rn(c0, c1);
                __half2 h23 = __floats2half2_rn(c2, c3);
                const int m0r = r0 + g, m1r = r0 + g + 8;
                const size_t a00 = ((size_t)((m0r >> 11) * 1024 + n))     * 2048 + (m0r & 2047);
                const size_t a01 = ((size_t)((m0r >> 11) * 1024 + n + 1)) * 2048 + (m0r & 2047);
                const size_t a10 = ((size_t)((m1r >> 11) * 1024 + n))     * 2048 + (m1r & 2047);
                const size_t a11 = ((size_t)((m1r >> 11) * 1024 + n + 1)) * 2048 + (m1r & 2047);
                YH[a00] = __low2half(h01);
                YH[a01] = __high2half(h01);
                YH[a10] = __low2half(h23);
                YH[a11] = __high2half(h23);
            }
        }
    }
}

// ---------------- persistent fused flash attention (pure-fp16 PV) -------------
// smem: buf0@0, buf1@33792 (each: KH 11264 | KL 11264 | VtH 11264)
//       mhist@67584 [32][128] f32 ; red@83968 [8][64] f32 ; s_unit@86016
#define ALD 88
#define ABUF 33792
#define AT_SMEM 86032
#define NUNITS 512

__global__ __launch_bounds__(256, 2) void attn_fused(float* __restrict__ atp) {
    extern __shared__ char sm[];
    const uint32_t smb = smem_u32(sm);
    float* mhist = (float*)(sm + 67584);
    float* red   = (float*)(sm + 83968);
    int* s_unit  = (int*)(sm + 86016);

    const int t = threadIdx.x;
    const int w = t >> 5;
    const int lane = t & 31;
    const int g = lane >> 2;
    const int tig = lane & 3;

    const int brow = (lane & 7) + ((lane >> 4) << 3);
    const int bcol = ((lane >> 3) & 1) * 8;

    const int r0c = t >> 3, c0c = t & 7;
    const int r1c = (t + 256) >> 3;

    while (true) {
        if (t == 0) *s_unit = atomicAdd(&g_ctr, 1);
        __syncthreads();
        const int u = *s_unit;
        if (u >= NUNITS) break;

        const int bh = u >> 4;            // same (b,h) adjacent -> K/V L2 reuse
        const int qt = u & 15;
        const int b = bh >> 4, h = bh & 15;
        const int q0 = qt * 128;
        const int blk = u;

        // ---- Q fragments ----
        uint32_t qh[4][4], ql[4][4];
        {
            const size_t rowA = (size_t)(b * SS + q0 + 16 * w + g) * DD + h * DK;
            const size_t rowB = (size_t)(b * SS + q0 + 16 * w + g + 8) * DD + h * DK;
#pragma unroll
            for (int j = 0; j < 4; ++j) {
                qh[j][0] = *(const uint32_t*)&g_QH[rowA + 16 * j + 2 * tig];
                qh[j][1] = *(const uint32_t*)&g_QH[rowB + 16 * j + 2 * tig];
                qh[j][2] = *(const uint32_t*)&g_QH[rowA + 16 * j + 8 + 2 * tig];
                qh[j][3] = *(const uint32_t*)&g_QH[rowB + 16 * j + 8 + 2 * tig];
                ql[j][0] = *(const uint32_t*)&g_QL[rowA + 16 * j + 2 * tig];
                ql[j][1] = *(const uint32_t*)&g_QL[rowB + 16 * j + 2 * tig];
                ql[j][2] = *(const uint32_t*)&g_QL[rowA + 16 * j + 8 + 2 * tig];
                ql[j][3] = *(const uint32_t*)&g_QL[rowB + 16 * j + 8 + 2 * tig];
            }
        }

        auto issueT = [&](int tile, int buf) {
            const uint32_t bb = smb + buf * ABUF;
            const size_t ksrc0 = (size_t)(b * SS + tile * 64 + r0c) * DD + h * DK + c0c * 8;
            const size_t ksrc1 = (size_t)(b * SS + tile * 64 + r1c) * DD + h * DK + c0c * 8;
            const size_t vsrc0 = (size_t)(b * 1024 + h * 64 + r0c) * 2048 + tile * 64 + c0c * 8;
            const size_t vsrc1 = (size_t)(b * 1024 + h * 64 + r1c) * 2048 + tile * 64 + c0c * 8;
            const uint32_t d0 = r0c * 176 + c0c * 16;
            const uint32_t d1 = r1c * 176 + c0c * 16;
            CP_ASYNC16(bb + d0,         g_KH + ksrc0);
            CP_ASYNC16(bb + d1,         g_KH + ksrc1);
            CP_ASYNC16(bb + 11264 + d0, g_KL + ksrc0);
            CP_ASYNC16(bb + 11264 + d1, g_KL + ksrc1);
            CP_ASYNC16(bb + 22528 + d0, g_VtH + vsrc0);
            CP_ASYNC16(bb + 22528 + d1, g_VtH + vsrc1);
        };

        float oacc[8][4];
#pragma unroll
        for (int ni = 0; ni < 8; ++ni)
#pragma unroll
            for (int j = 0; j < 4; ++j) oacc[ni][j] = 0.0f;

        float m0 = -INFINITY, m1 = -INFINITY, l0 = 0.0f, l1 = 0.0f;

        issueT(0, 0);
        CP_COMMIT();

        for (int tile = 0; tile < 32; ++tile) {
            const int buf = tile & 1;
            CP_WAIT0();
            __syncthreads();
            if (tile + 1 < 32) {
                issueT(tile + 1, buf ^ 1);
                CP_COMMIT();
            }
            const uint32_t bb = smb + buf * ABUF;

            // ---- QK^T (3-term, exact) ----
            float sacc[8][4];
#pragma unroll
            for (int ni = 0; ni < 8; ++ni)
#pragma unroll
                for (int j = 0; j < 4; ++j) sacc[ni][j] = 0.0f;

#pragma unroll
            for (int j = 0; j < 4; ++j) {
                const int k0 = 16 * j;
#pragma unroll
                for (int p = 0; p < 4; ++p) {
                    const uint32_t addr = bb + ((p * 16 + brow) * ALD + k0 + bcol) * 2;
                    uint32_t b0, b1, b2, b3, c0, c1, c2, c3;
                    ldsm_x4(b0, b1, b2, b3, addr);
                    ldsm_x4(c0, c1, c2, c3, addr + 11264);
                    mma_f16(sacc[2*p],   qh[j][0], qh[j][1], qh[j][2], qh[j][3], b0, b1);
                    mma_f16(sacc[2*p],   qh[j][0], qh[j][1], qh[j][2], qh[j][3], c0, c1);
                    mma_f16(sacc[2*p],   ql[j][0], ql[j][1], ql[j][2], ql[j][3], b0, b1);
                    mma_f16(sacc[2*p+1], qh[j][0], qh[j][1], qh[j][2], qh[j][3], b2, b3);
                    mma_f16(sacc[2*p+1], qh[j][0], qh[j][1], qh[j][2], qh[j][3], c2, c3);
                    mma_f16(sacc[2*p+1], ql[j][0], ql[j][1], ql[j][2], ql[j][3], b2, b3);
                }
            }

            // ---- scale + row max ----
            float mx0 = -INFINITY, mx1 = -INFINITY;
#pragma unroll
            for (int ni = 0; ni < 8; ++ni) {
                sacc[ni][0] *= SCALE; sacc[ni][1] *= SCALE;
                sacc[ni][2] *= SCALE; sacc[ni][3] *= SCALE;
                mx0 = fmaxf(mx0, fmaxf(sacc[ni][0], sacc[ni][1]));
                mx1 = fmaxf(mx1, fmaxf(sacc[ni][2], sacc[ni][3]));
            }
            mx0 = fmaxf(mx0, __shfl_xor_sync(0xffffffffu, mx0, 1));
            mx0 = fmaxf(mx0, __shfl_xor_sync(0xffffffffu, mx0, 2));
            mx1 = fmaxf(mx1, __shfl_xor_sync(0xffffffffu, mx1, 1));
            mx1 = fmaxf(mx1, __shfl_xor_sync(0xffffffffu, mx1, 2));

            const float mn0 = fmaxf(m0, mx0);
            const float mn1 = fmaxf(m1, mx1);
            const float al0 = __expf(m0 - mn0);
            const float al1 = __expf(m1 - mn1);
            m0 = mn0; m1 = mn1;

            // ---- u = exp(s-m); pack fp16 (PV A-frags); STG.128 scratch ----
            uint4* U4 = (uint4*)g_U + ((size_t)(blk * 32 + tile) * 4) * 256 + t;
            float ls0 = 0.0f, ls1 = 0.0f;
            uint32_t uf[8][2];
#pragma unroll
            for (int ni = 0; ni < 8; ++ni) {
                float u0 = __expf(sacc[ni][0] - m0);
                float u1 = __expf(sacc[ni][1] - m0);
                float u2 = __expf(sacc[ni][2] - m1);
                float u3 = __expf(sacc[ni][3] - m1);
                ls0 += u0 + u1; ls1 += u2 + u3;
                __half2 p01 = __floats2half2_rn(u0, u1);
                __half2 p23 = __floats2half2_rn(u2, u3);
                uf[ni][0] = *(uint32_t*)&p01;
                uf[ni][1] = *(uint32_t*)&p23;
                if (ni & 1) {
                    U4[(ni >> 1) * 256] = make_uint4(uf[ni-1][0], uf[ni-1][1],
                                                     uf[ni][0], uf[ni][1]);
                }
            }
            l0 = l0 * al0 + ls0;
            l1 = l1 * al1 + ls1;

            if (tig == 0) {
                mhist[tile * 128 + 16 * w + g]     = m0;
                mhist[tile * 128 + 16 * w + g + 8] = m1;
            }

#pragma unroll
            for (int ni = 0; ni < 8; ++ni) {
                oacc[ni][0] *= al0; oacc[ni][1] *= al0;
                oacc[ni][2] *= al1; oacc[ni][3] *= al1;
            }

            // ---- PV: pure fp16 ----
#pragma unroll
            for (int j = 0; j < 4; ++j) {
                const uint32_t a0 = uf[2*j][0],   a1 = uf[2*j][1];
                const uint32_t a2 = uf[2*j+1][0], a3 = uf[2*j+1][1];
                const int k0 = 16 * j;
#pragma unroll
                for (int p = 0; p < 4; ++p) {
                    const uint32_t addr = bb + 22528 + ((p * 16 + brow) * ALD + k0 + bcol) * 2;
                    uint32_t b0, b1, b2, b3;
                    ldsm_x4(b0, b1, b2, b3, addr);
                    mma_f16(oacc[2*p],   a0, a1, a2, a3, b0, b1);
                    mma_f16(oacc[2*p+1], a0, a1, a2, a3, b2, b3);
                }
            }
            __syncthreads();
        }

        // ---- finalize: merge l, write C hi-only fp16 ----
        l0 += __shfl_xor_sync(0xffffffffu, l0, 1);
        l0 += __shfl_xor_sync(0xffffffffu, l0, 2);
        l1 += __shfl_xor_sync(0xffffffffu, l1, 1);
        l1 += __shfl_xor_sync(0xffffffffu, l1, 2);
        const float il0 = 1.0f / l0;
        const float il1 = 1.0f / l1;

        {
            const size_t rowA = (size_t)(b * SS + q0 + 16 * w + g) * DD + h * DK;
            const size_t rowB = (size_t)(b * SS + q0 + 16 * w + g + 8) * DD + h * DK;
#pragma unroll
            for (int ni = 0; ni < 8; ++ni) {
                const int col = ni * 8 + 2 * tig;
                *(__half2*)&g_CH[rowA + col] =
                    __floats2half2_rn(oacc[ni][0] * il0, oacc[ni][1] * il0);
                *(__half2*)&g_CH[rowB + col] =
                    __floats2half2_rn(oacc[ni][2] * il1, oacc[ni][3] * il1);
            }
        }

        __syncthreads();

        // ---- colsum readback ----
        for (int tile = 0; tile < 32; ++tile) {
            const uint4* U4 = (const uint4*)g_U + ((size_t)(blk * 32 + tile) * 4) * 256 + t;
            uint32_t uu[16];
            *(uint4*)&uu[0]  = U4[0];
            *(uint4*)&uu[4]  = U4[256];
            *(uint4*)&uu[8]  = U4[512];
            *(uint4*)&uu[12] = U4[768];
            const float w0 = __expf(mhist[tile * 128 + 16 * w + g]     - m0) * il0;
            const float w1 = __expf(mhist[tile * 128 + 16 * w + g + 8] - m1) * il1;

#pragma unroll
            for (int ni = 0; ni < 8; ++ni) {
                float2 fa = __half22float2(*(__half2*)&uu[2 * ni]);
                float2 fb = __half22float2(*(__half2*)&uu[2 * ni + 1]);
                float cs0 = fa.x * w0 + fb.x * w1;
                float cs1 = fa.y * w0 + fb.y * w1;
                cs0 += __shfl_xor_sync(0xffffffffu, cs0, 4);
                cs0 += __shfl_xor_sync(0xffffffffu, cs0, 8);
                cs0 += __shfl_xor_sync(0xffffffffu, cs0, 16);
                cs1 += __shfl_xor_sync(0xffffffffu, cs1, 4);
                cs1 += __shfl_xor_sync(0xffffffffu, cs1, 8);
                cs1 += __shfl_xor_sync(0xffffffffu, cs1, 16);
                if (lane < 4) {
                    red[w * 64 + ni * 8 + 2 * tig]     = cs0;
                    red[w * 64 + ni * 8 + 2 * tig + 1] = cs1;
                }
            }
            __syncthreads();
            if (t < 64) {
                float s = 0.0f;
#pragma unroll
                for (int wi = 0; wi < 8; ++wi) s += red[wi * 64 + t];
                atomicAdd(&atp[b * SS + tile * 64 + t], s * INV_HS);
            }
            __syncthreads();
        }
    }
}

// ---------------- launch ------------------------------------------------------
extern "C" void kernel_launch(void* const* d_in, const int* in_sizes, int n_in,
                              void* d_out, int out_size) {
    (void)in_sizes; (void)n_in; (void)out_size;
    const float* query = (const float*)d_in[0];
    const float* key   = (const float*)d_in[1];
    const float* value = (const float*)d_in[2];
    const float* Wq = (const float*)d_in[3];
    const float* bq = (const float*)d_in[4];
    const float* Wk = (const float*)d_in[5];
    const float* bk = (const float*)d_in[6];
    const float* Wv = (const float*)d_in[7];
    const float* bv = (const float*)d_in[8];
    const float* Wo = (const float*)d_in[9];
    const float* bo = (const float*)d_in[10];

    float* out = (float*)d_out;
    float* atp = out + (size_t)BB * SS * DD;

    __half *inH, *inL, *QH, *QL, *KH, *KL, *VtH, *CH;
    cudaGetSymbolAddress((void**)&inH, g_inH);
    cudaGetSymbolAddress((void**)&inL, g_inL);
    cudaGetSymbolAddress((void**)&QH, g_QH);
    cudaGetSymbolAddress((void**)&QL, g_QL);
    cudaGetSymbolAddress((void**)&KH, g_KH);
    cudaGetSymbolAddress((void**)&KL, g_KL);
    cudaGetSymbolAddress((void**)&VtH, g_VtH);
    cudaGetSymbolAddress((void**)&CH, g_CH);

    zero_atp_kernel<<<(BB*SS + 255) / 256, 256>>>(atp);

    const int NX4 = MTOT * DD / 4;
    const int NW4 = DD * DD / 4;
    const size_t oQ = 0, oK = 4194304, oV = 8388608;
    const size_t oWq = 12582912, oWk = 13631488, oWv = 14680064, oWo = 15728640;
    split_kernel<<<NX4 / 256, 256>>>(query, inH + oQ,  inL + oQ,  NX4);
    split_kernel<<<NX4 / 256, 256>>>(key,   inH + oK,  inL + oK,  NX4);
    split_kernel<<<NX4 / 256, 256>>>(value, inH + oV,  inL + oV,  NX4);
    split_kernel<<<NW4 / 256, 256>>>(Wq, inH + oWq, inL + oWq, NW4);
    split_kernel<<<NW4 / 256, 256>>>(Wk, inH + oWk, inL + oWk, NW4);
    split_kernel<<<NW4 / 256, 256>>>(Wv, inH + oWv, inL + oWv, NW4);
    split_kernel<<<NW4 / 256, 256>>>(Wo, inH + oWo, inL + oWo, NW4);

    cudaFuncSetAttribute(gemm_h16<3>, cudaFuncAttributeMaxDynamicSharedMemorySize,
                         GEMM_SMEM);
    cudaFuncSetAttribute(gemm_h16<2>, cudaFuncAttributeMaxDynamicSharedMemorySize,
                         GEMM_SMEM);
    cudaFuncSetAttribute(attn_fused, cudaFuncAttributeMaxDynamicSharedMemorySize,
                         AT_SMEM);

    dim3 gg(GN / 128, MTOT / 128);
    gemm_h16<3><<<gg, 256, GEMM_SMEM>>>(inH + oQ, inL + oQ, inH + oWq, inL + oWq,
                                        bq, EP_H16, QH, QL, nullptr);
    gemm_h16<3><<<gg, 256, GEMM_SMEM>>>(inH + oK, inL + oK, inH + oWk, inL + oWk,
                                        bk, EP_H16, KH, KL, nullptr);
    gemm_h16<2><<<gg, 256, GEMM_SMEM>>>(inH + oV, nullptr, inH + oWv, inL + oWv,
                                        bv, EP_VT, VtH, nullptr, nullptr);

    attn_fused<<<296, 256, AT_SMEM>>>(atp);

    gemm_h16<2><<<gg, 256, GEMM_SMEM>>>(CH, nullptr, inH + oWo, inL + oWo,
                                        bo, EP_F32, nullptr, nullptr, out);
}

// round 16
// speedup vs baseline: 1.0431x; 1.0431x over previous
#include <cuda_runtime.h>
#include <cuda_fp16.h>
#include <math.h>
#include <stdint.h>

#define BB 2
#define SS 2048
#define DD 1024
#define HH 16
#define DK 64
#define MTOT (BB*SS)

#define SCALE 12.5f                  // 100/sqrt(64) (folded into Q epilogue)
#define INV_HS (1.0f/32768.0f)       // 1/(H*S)

// ---------------- device scratch ----------------------------------------------
__device__ __half g_inH[16777216];
__device__ __half g_inL[16777216];
__device__ __half g_QH[4194304], g_QL[4194304];   // pre-scaled by 12.5
__device__ __half g_KH[4194304], g_KL[4194304];
__device__ __half g_VtH[4194304];                 // [b*1024+n][2048] transposed
__device__ __half g_CH[4194304];
// u scratch (e4m3 x4 per word): chunk c of (blk,tile) at ((blk*32+tile)*2 + c)*256 + t (uint4 granules)
__device__ uint32_t g_U[512ull * 32 * 8 * 256];
__device__ int g_ctr;

// ---------------- helpers -----------------------------------------------------
__device__ __forceinline__ void split_h2(float a, float b, __half2& h, __half2& l) {
    h = __floats2half2_rn(a, b);
    float2 f = __half22float2(h);
    l = __floats2half2_rn(a - f.x, b - f.y);
}

__device__ __forceinline__ void mma_f16(float c[4],
                                        uint32_t a0, uint32_t a1, uint32_t a2, uint32_t a3,
                                        uint32_t b0, uint32_t b1) {
    asm volatile(
        "mma.sync.aligned.m16n8k16.row.col.f32.f16.f16.f32 "
        "{%0,%1,%2,%3}, {%4,%5,%6,%7}, {%8,%9}, {%0,%1,%2,%3};"
        : "+f"(c[0]), "+f"(c[1]), "+f"(c[2]), "+f"(c[3])
        : "r"(a0), "r"(a1), "r"(a2), "r"(a3), "r"(b0), "r"(b1));
}

__device__ __forceinline__ void ldsm_x4(uint32_t& r0, uint32_t& r1,
                                        uint32_t& r2, uint32_t& r3, uint32_t addr) {
    asm volatile("ldmatrix.sync.aligned.m8n8.x4.shared.b16 {%0,%1,%2,%3}, [%4];"
        : "=r"(r0), "=r"(r1), "=r"(r2), "=r"(r3) : "r"(addr));
}

__device__ __forceinline__ uint32_t smem_u32(const void* p) {
    uint32_t a;
    asm("{ .reg .u64 t; cvta.to.shared.u64 t, %1; cvt.u32.u64 %0, t; }"
        : "=r"(a) : "l"(p));
    return a;
}

// pack 4 floats -> 4 e4m3 bytes (lo16 = (u0,u1), hi16 = (u2,u3))
__device__ __forceinline__ uint32_t pack4_e4m3(float u0, float u1, float u2, float u3) {
    uint16_t p01, p23;
    asm("cvt.rn.satfinite.e4m3x2.f32 %0, %1, %2;" : "=h"(p01) : "f"(u1), "f"(u0));
    asm("cvt.rn.satfinite.e4m3x2.f32 %0, %1, %2;" : "=h"(p23) : "f"(u3), "f"(u2));
    return (uint32_t)p01 | ((uint32_t)p23 << 16);
}

__device__ __forceinline__ float2 unpack2_e4m3(uint16_t p) {
    uint32_t h2;
    asm("cvt.rn.f16x2.e4m3x2 %0, %1;" : "=r"(h2) : "h"(p));
    return __half22float2(*(__half2*)&h2);
}

#define CP_ASYNC16(dst, src) \
    asm volatile("cp.async.cg.shared.global [%0], [%1], 16;" :: "r"(dst), "l"(src))
#define CP_COMMIT() asm volatile("cp.async.commit_group;" ::: "memory")
#define CP_WAIT0()  asm volatile("cp.async.wait_group 0;" ::: "memory")

// ---------------- zero mean_atp + reset work counter ---------------------------
__global__ void zero_atp_kernel(float* __restrict__ atp) {
    int i = blockIdx.x * blockDim.x + threadIdx.x;
    if (i < BB*SS) atp[i] = 0.0f;
    if (i == 0) g_ctr = 0;
}

// ---------------- fused pre-split kernels --------------------------------------
__device__ __forceinline__ void split_store(const float* __restrict__ src,
                                            __half* __restrict__ H,
                                            __half* __restrict__ L, int i) {
    float4 v = ((const float4*)src)[i];
    __half2 h01, l01, h23, l23;
    split_h2(v.x, v.y, h01, l01);
    split_h2(v.z, v.w, h23, l23);
    ((__half2*)H)[2*i]   = h01;
    ((__half2*)H)[2*i+1] = h23;
    ((__half2*)L)[2*i]   = l01;
    ((__half2*)L)[2*i+1] = l23;
}

__global__ void split_in3(const float* __restrict__ q, const float* __restrict__ k,
                          const float* __restrict__ v,
                          __half* __restrict__ H, __half* __restrict__ L, int n4) {
    int i = blockIdx.x * blockDim.x + threadIdx.x;
    if (i >= n4) return;
    const float* src = (blockIdx.y == 0) ? q : (blockIdx.y == 1) ? k : v;
    size_t off = (size_t)blockIdx.y * n4 * 4;
    split_store(src, H + off, L + off, i);
}

__global__ void split_w4(const float* __restrict__ w0, const float* __restrict__ w1,
                         const float* __restrict__ w2, const float* __restrict__ w3,
                         __half* __restrict__ H, __half* __restrict__ L, int n4) {
    int i = blockIdx.x * blockDim.x + threadIdx.x;
    if (i >= n4) return;
    const float* src = (blockIdx.y == 0) ? w0 : (blockIdx.y == 1) ? w1
                     : (blockIdx.y == 2) ? w2 : w3;
    size_t off = (size_t)blockIdx.y * n4 * 4;
    split_store(src, H + off, L + off, i);
}

// ---------------- templated fp16 GEMM (3-term or 2-term) ----------------------
#define GK 1024
#define GN 1024
#define LDH 40
#define MAT_B 10240
#define BUF_B 40960
#define GEMM_SMEM 81920
#define EP_H16 0
#define EP_VT 1
#define EP_F32 2

template<int NT>
__global__ __launch_bounds__(256, 2) void gemm_h16(
    const __half* __restrict__ XH, const __half* __restrict__ XL,
    const __half* __restrict__ WH, const __half* __restrict__ WL,
    const float* __restrict__ bias, int mode, float oscale,
    __half* __restrict__ YH, __half* __restrict__ YL, float* __restrict__ YF)
{
    extern __shared__ char sm[];
    const uint32_t smb = smem_u32(sm);

    const int t = threadIdx.x;
    const int w = t >> 5;
    const int lane = t & 31;
    const int g = lane >> 2;
    const int tig = lane & 3;
    const int warp_m = (w >> 2) * 64;
    const int warp_n = (w & 3) * 32;
    const int bm = blockIdx.y * 128;
    const int bn = blockIdx.x * 128;

    const int arow = lane & 15;
    const int acol = (lane >> 4) * 8;
    const int brow = (lane & 7) + ((lane >> 4) << 3);
    const int bcol = ((lane >> 3) & 1) * 8;

    const int r0c = t >> 2, c0c = t & 3;
    const int r1c = (t + 256) >> 2;

    float acc[4][4][4];
#pragma unroll
    for (int mi = 0; mi < 4; ++mi)
#pragma unroll
        for (int ni = 0; ni < 4; ++ni)
#pragma unroll
            for (int j = 0; j < 4; ++j) acc[mi][ni][j] = 0.0f;

    const int NS = GK / 32;

    auto issue = [&](int s, int buf) {
        const uint32_t bb = smb + buf * BUF_B;
        const size_t ks = (size_t)s * 32;
        CP_ASYNC16(bb + r0c * 80 + c0c * 16, XH + (size_t)(bm + r0c) * GK + ks + c0c * 8);
        CP_ASYNC16(bb + r1c * 80 + c0c * 16, XH + (size_t)(bm + r1c) * GK + ks + c0c * 8);
        if (NT == 3) {
            CP_ASYNC16(bb + MAT_B + r0c * 80 + c0c * 16, XL + (size_t)(bm + r0c) * GK + ks + c0c * 8);
            CP_ASYNC16(bb + MAT_B + r1c * 80 + c0c * 16, XL + (size_t)(bm + r1c) * GK + ks + c0c * 8);
        }
        CP_ASYNC16(bb + 2 * MAT_B + r0c * 80 + c0c * 16, WH + (size_t)(bn + r0c) * GK + ks + c0c * 8);
        CP_ASYNC16(bb + 2 * MAT_B + r1c * 80 + c0c * 16, WH + (size_t)(bn + r1c) * GK + ks + c0c * 8);
        CP_ASYNC16(bb + 3 * MAT_B + r0c * 80 + c0c * 16, WL + (size_t)(bn + r0c) * GK + ks + c0c * 8);
        CP_ASYNC16(bb + 3 * MAT_B + r1c * 80 + c0c * 16, WL + (size_t)(bn + r1c) * GK + ks + c0c * 8);
    };

    issue(0, 0);
    CP_COMMIT();

    for (int s = 0; s < NS; ++s) {
        const int buf = s & 1;
        CP_WAIT0();
        __syncthreads();
        if (s + 1 < NS) {
            issue(s + 1, buf ^ 1);
            CP_COMMIT();
        }

        const uint32_t xb = smb + buf * BUF_B;
        const uint32_t wb = xb + 2 * MAT_B;

#pragma unroll
        for (int k16 = 0; k16 < 2; ++k16) {
            const int k0 = k16 * 16;
            uint32_t bh[4][2], bl[4][2];
#pragma unroll
            for (int p = 0; p < 2; ++p) {
                const uint32_t addr = wb + ((warp_n + p * 16 + brow) * LDH + k0 + bcol) * 2;
                ldsm_x4(bh[2*p][0], bh[2*p][1], bh[2*p+1][0], bh[2*p+1][1], addr);
                ldsm_x4(bl[2*p][0], bl[2*p][1], bl[2*p+1][0], bl[2*p+1][1], addr + MAT_B);
            }
#pragma unroll
            for (int mi = 0; mi < 4; ++mi) {
                const uint32_t addrA = xb + ((warp_m + mi * 16 + arow) * LDH + k0 + acol) * 2;
                uint32_t ah[4], al[4];
                ldsm_x4(ah[0], ah[1], ah[2], ah[3], addrA);
                if (NT == 3)
                    ldsm_x4(al[0], al[1], al[2], al[3], addrA + MAT_B);
#pragma unroll
                for (int ni = 0; ni < 4; ++ni) {
                    mma_f16(acc[mi][ni], ah[0], ah[1], ah[2], ah[3], bh[ni][0], bh[ni][1]);
                    mma_f16(acc[mi][ni], ah[0], ah[1], ah[2], ah[3], bl[ni][0], bl[ni][1]);
                    if (NT == 3)
                        mma_f16(acc[mi][ni], al[0], al[1], al[2], al[3], bh[ni][0], bh[ni][1]);
                }
            }
        }
        __syncthreads();
    }

    // ---- epilogue ----
#pragma unroll
    for (int ni = 0; ni < 4; ++ni) {
        const int n = bn + warp_n + ni * 8 + 2 * tig;
        const float2 b2 = *(const float2*)(bias + n);
#pragma unroll
        for (int mi = 0; mi < 4; ++mi) {
            const int r0 = bm + warp_m + mi * 16;
            float c0 = acc[mi][ni][0] + b2.x, c1 = acc[mi][ni][1] + b2.y;
            float c2 = acc[mi][ni][2] + b2.x, c3 = acc[mi][ni][3] + b2.y;
            if (mode == EP_F32) {
                *(float2*)(YF + (size_t)(r0 + g) * GN + n)     = make_float2(c0, c1);
                *(float2*)(YF + (size_t)(r0 + g + 8) * GN + n) = make_float2(c2, c3);
            } else if (mode == EP_H16) {
                c0 *= oscale; c1 *= oscale; c2 *= oscale; c3 *= oscale;
                __half2 h01, l01, h23, l23;
                split_h2(c0, c1, h01, l01);
                split_h2(c2, c3, h23, l23);
                *(__half2*)(YH + (size_t)(r0 + g) * GN + n)     = h01;
                *(__half2*)(YL + (size_t)(r0 + g) * GN + n)     = l01;
                *(__half2*)(YH + (size_t)(r0 + g + 8) * GN + n) = h23;
                *(__half2*)(YL + (size_t)(r0 + g + 8) * GN + n) = l23;
            } else {   // EP_VT: hi only
                __half2 h01 = __floats2half2_rn(c0, c1);
                __half2 h23 = __floats2half2_rn(c2, c3);
                const int m0r = r0 + g, m1r = r0 + g + 8;
                const size_t a00 = ((size_t)((m0r >> 11) * 1024 + n))     * 2048 + (m0r & 2047);
                const size_t a01 = ((size_t)((m0r >> 11) * 1024 + n + 1)) * 2048 + (m0r & 2047);
                const size_t a10 = ((size_t)((m1r >> 11) * 1024 + n))     * 2048 + (m1r & 2047);
                const size_t a11 = ((size_t)((m1r >> 11) * 1024 + n + 1)) * 2048 + (m1r & 2047);
                YH[a00] = __low2half(h01);
                YH[a01] = __high2half(h01);
                YH[a10] = __low2half(h23);
                YH[a11] = __high2half(h23);
            }
        }
    }
}

// ---------------- persistent fused flash attention -----------------------------
// smem: buf0@0, buf1@33792 (each: KH 11264 | KL 11264 | VtH 11264)
//       mhist@67584 [32][128] f32 ; red@83968 [8][64] f32 ; s_unit@86016
#define ALD 88
#define ABUF 33792
#define AT_SMEM 86032
#define NUNITS 512

__global__ __launch_bounds__(256, 2) void attn_fused(float* __restrict__ atp) {
    extern __shared__ char sm[];
    const uint32_t smb = smem_u32(sm);
    float* mhist = (float*)(sm + 67584);
    float* red   = (float*)(sm + 83968);
    int* s_unit  = (int*)(sm + 86016);

    const int t = threadIdx.x;
    const int w = t >> 5;
    const int lane = t & 31;
    const int g = lane >> 2;
    const int tig = lane & 3;

    const int brow = (lane & 7) + ((lane >> 4) << 3);
    const int bcol = ((lane >> 3) & 1) * 8;

    const int r0c = t >> 3, c0c = t & 7;
    const int r1c = (t + 256) >> 3;

    while (true) {
        if (t == 0) *s_unit = atomicAdd(&g_ctr, 1);
        __syncthreads();
        const int u = *s_unit;
        if (u >= NUNITS) break;

        const int bh = u >> 4;
        const int qt = u & 15;
        const int b = bh >> 4, h = bh & 15;
        const int q0 = qt * 128;
        const int blk = u;

        // ---- Q fragments (pre-scaled by 12.5) ----
        uint32_t qh[4][4], ql[4][4];
        {
            const size_t rowA = (size_t)(b * SS + q0 + 16 * w + g) * DD + h * DK;
            const size_t rowB = (size_t)(b * SS + q0 + 16 * w + g + 8) * DD + h * DK;
#pragma unroll
            for (int j = 0; j < 4; ++j) {
                qh[j][0] = *(const uint32_t*)&g_QH[rowA + 16 * j + 2 * tig];
                qh[j][1] = *(const uint32_t*)&g_QH[rowB + 16 * j + 2 * tig];
                qh[j][2] = *(const uint32_t*)&g_QH[rowA + 16 * j + 8 + 2 * tig];
                qh[j][3] = *(const uint32_t*)&g_QH[rowB + 16 * j + 8 + 2 * tig];
                ql[j][0] = *(const uint32_t*)&g_QL[rowA + 16 * j + 2 * tig];
                ql[j][1] = *(const uint32_t*)&g_QL[rowB + 16 * j + 2 * tig];
                ql[j][2] = *(const uint32_t*)&g_QL[rowA + 16 * j + 8 + 2 * tig];
                ql[j][3] = *(const uint32_t*)&g_QL[rowB + 16 * j + 8 + 2 * tig];
            }
        }

        auto issueT = [&](int tile, int buf) {
            const uint32_t bb = smb + buf * ABUF;
            const size_t ksrc0 = (size_t)(b * SS + tile * 64 + r0c) * DD + h * DK + c0c * 8;
            const size_t ksrc1 = (size_t)(b * SS + tile * 64 + r1c) * DD + h * DK + c0c * 8;
            const size_t vsrc0 = (size_t)(b * 1024 + h * 64 + r0c) * 2048 + tile * 64 + c0c * 8;
            const size_t vsrc1 = (size_t)(b * 1024 + h * 64 + r1c) * 2048 + tile * 64 + c0c * 8;
            const uint32_t d0 = r0c * 176 + c0c * 16;
            const uint32_t d1 = r1c * 176 + c0c * 16;
            CP_ASYNC16(bb + d0,         g_KH + ksrc0);
            CP_ASYNC16(bb + d1,         g_KH + ksrc1);
            CP_ASYNC16(bb + 11264 + d0, g_KL + ksrc0);
            CP_ASYNC16(bb + 11264 + d1, g_KL + ksrc1);
            CP_ASYNC16(bb + 22528 + d0, g_VtH + vsrc0);
            CP_ASYNC16(bb + 22528 + d1, g_VtH + vsrc1);
        };

        float oacc[8][4];
#pragma unroll
        for (int ni = 0; ni < 8; ++ni)
#pragma unroll
            for (int j = 0; j < 4; ++j) oacc[ni][j] = 0.0f;

        float m0 = -INFINITY, m1 = -INFINITY, l0 = 0.0f, l1 = 0.0f;

        issueT(0, 0);
        CP_COMMIT();

        for (int tile = 0; tile < 32; ++tile) {
            const int buf = tile & 1;
            CP_WAIT0();
            __syncthreads();
            if (tile + 1 < 32) {
                issueT(tile + 1, buf ^ 1);
                CP_COMMIT();
            }
            const uint32_t bb = smb + buf * ABUF;

            // ---- QK^T (3-term, exact; scale pre-folded into Q) ----
            float sacc[8][4];
#pragma unroll
            for (int ni = 0; ni < 8; ++ni)
#pragma unroll
                for (int j = 0; j < 4; ++j) sacc[ni][j] = 0.0f;

#pragma unroll
            for (int j = 0; j < 4; ++j) {
                const int k0 = 16 * j;
#pragma unroll
                for (int p = 0; p < 4; ++p) {
                    const uint32_t addr = bb + ((p * 16 + brow) * ALD + k0 + bcol) * 2;
                    uint32_t b0, b1, b2, b3, c0, c1, c2, c3;
                    ldsm_x4(b0, b1, b2, b3, addr);
                    ldsm_x4(c0, c1, c2, c3, addr + 11264);
                    mma_f16(sacc[2*p],   qh[j][0], qh[j][1], qh[j][2], qh[j][3], b0, b1);
                    mma_f16(sacc[2*p],   qh[j][0], qh[j][1], qh[j][2], qh[j][3], c0, c1);
                    mma_f16(sacc[2*p],   ql[j][0], ql[j][1], ql[j][2], ql[j][3], b0, b1);
                    mma_f16(sacc[2*p+1], qh[j][0], qh[j][1], qh[j][2], qh[j][3], b2, b3);
                    mma_f16(sacc[2*p+1], qh[j][0], qh[j][1], qh[j][2], qh[j][3], c2, c3);
                    mma_f16(sacc[2*p+1], ql[j][0], ql[j][1], ql[j][2], ql[j][3], b2, b3);
                }
            }

            // ---- row max ----
            float mx0 = -INFINITY, mx1 = -INFINITY;
#pragma unroll
            for (int ni = 0; ni < 8; ++ni) {
                mx0 = fmaxf(mx0, fmaxf(sacc[ni][0], sacc[ni][1]));
                mx1 = fmaxf(mx1, fmaxf(sacc[ni][2], sacc[ni][3]));
            }
            mx0 = fmaxf(mx0, __shfl_xor_sync(0xffffffffu, mx0, 1));
            mx0 = fmaxf(mx0, __shfl_xor_sync(0xffffffffu, mx0, 2));
            mx1 = fmaxf(mx1, __shfl_xor_sync(0xffffffffu, mx1, 1));
            mx1 = fmaxf(mx1, __shfl_xor_sync(0xffffffffu, mx1, 2));

            const float mn0 = fmaxf(m0, mx0);
            const float mn1 = fmaxf(m1, mx1);
            const float al0 = __expf(m0 - mn0);
            const float al1 = __expf(m1 - mn1);
            m0 = mn0; m1 = mn1;

            // ---- u = exp(s-m); fp16 packs for PV; e4m3 packs to scratch ----
            float ls0 = 0.0f, ls1 = 0.0f;
            uint32_t uf[8][2];
            uint32_t u8[8];
#pragma unroll
            for (int ni = 0; ni < 8; ++ni) {
                float u0 = __expf(sacc[ni][0] - m0);
                float u1 = __expf(sacc[ni][1] - m0);
                float u2 = __expf(sacc[ni][2] - m1);
                float u3 = __expf(sacc[ni][3] - m1);
                ls0 += u0 + u1; ls1 += u2 + u3;
                __half2 p01 = __floats2half2_rn(u0, u1);
                __half2 p23 = __floats2half2_rn(u2, u3);
                uf[ni][0] = *(uint32_t*)&p01;
                uf[ni][1] = *(uint32_t*)&p23;
                u8[ni] = pack4_e4m3(u0, u1, u2, u3);
            }
            {
                uint4* U4 = (uint4*)g_U + ((size_t)(blk * 32 + tile) * 2) * 256 + t;
                U4[0]   = make_uint4(u8[0], u8[1], u8[2], u8[3]);
                U4[256] = make_uint4(u8[4], u8[5], u8[6], u8[7]);
            }
            l0 = l0 * al0 + ls0;
            l1 = l1 * al1 + ls1;

            if (tig == 0) {
                mhist[tile * 128 + 16 * w + g]     = m0;
                mhist[tile * 128 + 16 * w + g + 8] = m1;
            }

#pragma unroll
            for (int ni = 0; ni < 8; ++ni) {
                oacc[ni][0] *= al0; oacc[ni][1] *= al0;
                oacc[ni][2] *= al1; oacc[ni][3] *= al1;
            }

            // ---- PV: pure fp16 ----
#pragma unroll
            for (int j = 0; j < 4; ++j) {
                const uint32_t a0 = uf[2*j][0],   a1 = uf[2*j][1];
                const uint32_t a2 = uf[2*j+1][0], a3 = uf[2*j+1][1];
                const int k0 = 16 * j;
#pragma unroll
                for (int p = 0; p < 4; ++p) {
                    const uint32_t addr = bb + 22528 + ((p * 16 + brow) * ALD + k0 + bcol) * 2;
                    uint32_t b0, b1, b2, b3;
                    ldsm_x4(b0, b1, b2, b3, addr);
                    mma_f16(oacc[2*p],   a0, a1, a2, a3, b0, b1);
                    mma_f16(oacc[2*p+1], a0, a1, a2, a3, b2, b3);
                }
            }
            __syncthreads();
        }

        // ---- finalize ----
        l0 += __shfl_xor_sync(0xffffffffu, l0, 1);
        l0 += __shfl_xor_sync(0xffffffffu, l0, 2);
        l1 += __shfl_xor_sync(0xffffffffu, l1, 1);
        l1 += __shfl_xor_sync(0xffffffffu, l1, 2);
        const float il0 = 1.0f / l0;
        const float il1 = 1.0f / l1;

        {
            const size_t rowA = (size_t)(b * SS + q0 + 16 * w + g) * DD + h * DK;
            const size_t rowB = (size_t)(b * SS + q0 + 16 * w + g + 8) * DD + h * DK;
#pragma unroll
            for (int ni = 0; ni < 8; ++ni) {
                const int col = ni * 8 + 2 * tig;
                *(__half2*)&g_CH[rowA + col] =
                    __floats2half2_rn(oacc[ni][0] * il0, oacc[ni][1] * il0);
                *(__half2*)&g_CH[rowB + col] =
                    __floats2half2_rn(oacc[ni][2] * il1, oacc[ni][3] * il1);
            }
        }

        __syncthreads();

        // ---- colsum readback (e4m3) ----
        for (int tile = 0; tile < 32; ++tile) {
            const uint4* U4 = (const uint4*)g_U + ((size_t)(blk * 32 + tile) * 2) * 256 + t;
            uint32_t uu[8];
            *(uint4*)&uu[0] = U4[0];
            *(uint4*)&uu[4] = U4[256];
            const float w0 = __expf(mhist[tile * 128 + 16 * w + g]     - m0) * il0;
            const float w1 = __expf(mhist[tile * 128 + 16 * w + g + 8] - m1) * il1;

#pragma unroll
            for (int ni = 0; ni < 8; ++ni) {
                float2 fa = unpack2_e4m3((uint16_t)(uu[ni] & 0xFFFF));   // (u0,u1) row g
                float2 fb = unpack2_e4m3((uint16_t)(uu[ni] >> 16));      // (u2,u3) row g+8
                float cs0 = fa.x * w0 + fb.x * w1;
                float cs1 = fa.y * w0 + fb.y * w1;
                cs0 += __shfl_xor_sync(0xffffffffu, cs0, 4);
                cs0 += __shfl_xor_sync(0xffffffffu, cs0, 8);
                cs0 += __shfl_xor_sync(0xffffffffu, cs0, 16);
                cs1 += __shfl_xor_sync(0xffffffffu, cs1, 4);
                cs1 += __shfl_xor_sync(0xffffffffu, cs1, 8);
                cs1 += __shfl_xor_sync(0xffffffffu, cs1, 16);
                if (lane < 4) {
                    red[w * 64 + ni * 8 + 2 * tig]     = cs0;
                    red[w * 64 + ni * 8 + 2 * tig + 1] = cs1;
                }
            }
            __syncthreads();
            if (t < 64) {
                float s = 0.0f;
#pragma unroll
                for (int wi = 0; wi < 8; ++wi) s += red[wi * 64 + t];
                atomicAdd(&atp[b * SS + tile * 64 + t], s * INV_HS);
            }
            __syncthreads();
        }
    }
}

// ---------------- launch ------------------------------------------------------
extern "C" void kernel_launch(void* const* d_in, const int* in_sizes, int n_in,
                              void* d_out, int out_size) {
    (void)in_sizes; (void)n_in; (void)out_size;
    const float* query = (const float*)d_in[0];
    const float* key   = (const float*)d_in[1];
    const float* value = (const float*)d_in[2];
    const float* Wq = (const float*)d_in[3];
    const float* bq = (const float*)d_in[4];
    const float* Wk = (const float*)d_in[5];
    const float* bk = (const float*)d_in[6];
    const float* Wv = (const float*)d_in[7];
    const float* bv = (const float*)d_in[8];
    const float* Wo = (const float*)d_in[9];
    const float* bo = (const float*)d_in[10];

    float* out = (float*)d_out;
    float* atp = out + (size_t)BB * SS * DD;

    __half *inH, *inL, *QH, *QL, *KH, *KL, *VtH, *CH;
    cudaGetSymbolAddress((void**)&inH, g_inH);
    cudaGetSymbolAddress((void**)&inL, g_inL);
    cudaGetSymbolAddress((void**)&QH, g_QH);
    cudaGetSymbolAddress((void**)&QL, g_QL);
    cudaGetSymbolAddress((void**)&KH, g_KH);
    cudaGetSymbolAddress((void**)&KL, g_KL);
    cudaGetSymbolAddress((void**)&VtH, g_VtH);
    cudaGetSymbolAddress((void**)&CH, g_CH);

    zero_atp_kernel<<<(BB*SS + 255) / 256, 256>>>(atp);

    const int NX4 = MTOT * DD / 4;          // 1048576
    const int NW4 = DD * DD / 4;            // 262144
    const size_t oWq = 12582912;
    split_in3<<<dim3(NX4 / 256, 3), 256>>>(query, key, value, inH, inL, NX4);
    split_w4<<<dim3(NW4 / 256, 4), 256>>>(Wq, Wk, Wv, Wo, inH + oWq, inL + oWq, NW4);

    cudaFuncSetAttribute(gemm_h16<3>, cudaFuncAttributeMaxDynamicSharedMemorySize,
                         GEMM_SMEM);
    cudaFuncSetAttribute(gemm_h16<2>, cudaFuncAttributeMaxDynamicSharedMemorySize,
                         GEMM_SMEM);
    cudaFuncSetAttribute(attn_fused, cudaFuncAttributeMaxDynamicSharedMemorySize,
                         AT_SMEM);

    const size_t oQ = 0, oK = 4194304, oV = 8388608;
    const size_t oWk = 13631488, oWv = 14680064, oWo = 15728640;
    dim3 gg(GN / 128, MTOT / 128);
    gemm_h16<3><<<gg, 256, GEMM_SMEM>>>(inH + oQ, inL + oQ, inH + oWq, inL + oWq,
                                        bq, EP_H16, SCALE, QH, QL, nullptr);
    gemm_h16<3><<<gg, 256, GEMM_SMEM>>>(inH + oK, inL + oK, inH + oWk, inL + oWk,
                                        bk, EP_H16, 1.0f, KH, KL, nullptr);
    gemm_h16<2><<<gg, 256, GEMM_SMEM>>>(inH + oV, nullptr, inH + oWv, inL + oWv,
                                        bv, EP_VT, 1.0f, VtH, nullptr, nullptr);

    attn_fused<<<296, 256, AT_SMEM>>>(atp);

    gemm_h16<2><<<gg, 256, GEMM_SMEM>>>(CH, nullptr, inH + oWo, inL + oWo,
                                        bo, EP_F32, 1.0f, nullptr, nullptr, out);
}

// round 17
// speedup vs baseline: 1.1303x; 1.0836x over previous
#include <cuda_runtime.h>
#include <cuda_fp16.h>
#include <math.h>
#include <stdint.h>

#define BB 2
#define SS 2048
#define DD 1024
#define HH 16
#define DK 64
#define MTOT (BB*SS)

#define SCALE 12.5f                  // 100/sqrt(64) (folded into Q epilogue)
#define INV_HS (1.0f/32768.0f)       // 1/(H*S)

// ---------------- device scratch ----------------------------------------------
__device__ __half g_inH[16777216];
__device__ __half g_inL[16777216];
__device__ __half g_QH[4194304], g_QL[4194304];   // pre-scaled by 12.5
__device__ __half g_KH[4194304], g_KL[4194304];
__device__ __half g_VtH[4194304];                 // [b*1024+n][2048] transposed
__device__ __half g_CH[4194304];
// u scratch (e4m3 x4 per word): chunk c of (blk,tile) at ((blk*32+tile)*2 + c)*256 + t
__device__ uint32_t g_U[512ull * 32 * 8 * 256];
__device__ int g_ctr;

// ---------------- helpers -----------------------------------------------------
__device__ __forceinline__ void split_h2(float a, float b, __half2& h, __half2& l) {
    h = __floats2half2_rn(a, b);
    float2 f = __half22float2(h);
    l = __floats2half2_rn(a - f.x, b - f.y);
}

__device__ __forceinline__ void mma_f16(float c[4],
                                        uint32_t a0, uint32_t a1, uint32_t a2, uint32_t a3,
                                        uint32_t b0, uint32_t b1) {
    asm volatile(
        "mma.sync.aligned.m16n8k16.row.col.f32.f16.f16.f32 "
        "{%0,%1,%2,%3}, {%4,%5,%6,%7}, {%8,%9}, {%0,%1,%2,%3};"
        : "+f"(c[0]), "+f"(c[1]), "+f"(c[2]), "+f"(c[3])
        : "r"(a0), "r"(a1), "r"(a2), "r"(a3), "r"(b0), "r"(b1));
}

__device__ __forceinline__ void ldsm_x4(uint32_t& r0, uint32_t& r1,
                                        uint32_t& r2, uint32_t& r3, uint32_t addr) {
    asm volatile("ldmatrix.sync.aligned.m8n8.x4.shared.b16 {%0,%1,%2,%3}, [%4];"
        : "=r"(r0), "=r"(r1), "=r"(r2), "=r"(r3) : "r"(addr));
}

__device__ __forceinline__ uint32_t smem_u32(const void* p) {
    uint32_t a;
    asm("{ .reg .u64 t; cvta.to.shared.u64 t, %1; cvt.u32.u64 %0, t; }"
        : "=r"(a) : "l"(p));
    return a;
}

__device__ __forceinline__ uint32_t pack4_e4m3(float u0, float u1, float u2, float u3) {
    uint16_t p01, p23;
    asm("cvt.rn.satfinite.e4m3x2.f32 %0, %1, %2;" : "=h"(p01) : "f"(u1), "f"(u0));
    asm("cvt.rn.satfinite.e4m3x2.f32 %0, %1, %2;" : "=h"(p23) : "f"(u3), "f"(u2));
    return (uint32_t)p01 | ((uint32_t)p23 << 16);
}

__device__ __forceinline__ float2 unpack2_e4m3(uint16_t p) {
    uint32_t h2;
    asm("cvt.rn.f16x2.e4m3x2 %0, %1;" : "=r"(h2) : "h"(p));
    return __half22float2(*(__half2*)&h2);
}

#define CP_ASYNC16(dst, src) \
    asm volatile("cp.async.cg.shared.global [%0], [%1], 16;" :: "r"(dst), "l"(src))
#define CP_COMMIT() asm volatile("cp.async.commit_group;" ::: "memory")
#define CP_WAIT0()  asm volatile("cp.async.wait_group 0;" ::: "memory")

// ---------------- zero mean_atp + reset work counter ---------------------------
__global__ void zero_atp_kernel(float* __restrict__ atp) {
    int i = blockIdx.x * blockDim.x + threadIdx.x;
    if (i < BB*SS) atp[i] = 0.0f;
    if (i == 0) g_ctr = 0;
}

// ---------------- fused pre-split kernels --------------------------------------
__device__ __forceinline__ void split_store(const float* __restrict__ src,
                                            __half* __restrict__ H,
                                            __half* __restrict__ L, int i) {
    float4 v = ((const float4*)src)[i];
    __half2 h01, l01, h23, l23;
    split_h2(v.x, v.y, h01, l01);
    split_h2(v.z, v.w, h23, l23);
    ((__half2*)H)[2*i]   = h01;
    ((__half2*)H)[2*i+1] = h23;
    ((__half2*)L)[2*i]   = l01;
    ((__half2*)L)[2*i+1] = l23;
}

__global__ void split_in3(const float* __restrict__ q, const float* __restrict__ k,
                          const float* __restrict__ v,
                          __half* __restrict__ H, __half* __restrict__ L, int n4) {
    int i = blockIdx.x * blockDim.x + threadIdx.x;
    if (i >= n4) return;
    const float* src = (blockIdx.y == 0) ? q : (blockIdx.y == 1) ? k : v;
    size_t off = (size_t)blockIdx.y * n4 * 4;
    split_store(src, H + off, L + off, i);
}

__global__ void split_w4(const float* __restrict__ w0, const float* __restrict__ w1,
                         const float* __restrict__ w2, const float* __restrict__ w3,
                         __half* __restrict__ H, __half* __restrict__ L, int n4) {
    int i = blockIdx.x * blockDim.x + threadIdx.x;
    if (i >= n4) return;
    const float* src = (blockIdx.y == 0) ? w0 : (blockIdx.y == 1) ? w1
                     : (blockIdx.y == 2) ? w2 : w3;
    size_t off = (size_t)blockIdx.y * n4 * 4;
    split_store(src, H + off, L + off, i);
}

// ---------------- templated fp16 GEMM (NT = 1, 2, or 3 terms) -----------------
#define GK 1024
#define GN 1024
#define LDH 40
#define MAT_B 10240
#define BUF_B 40960
#define GEMM_SMEM 81920
#define EP_H16 0
#define EP_VT 1
#define EP_F32 2

template<int NT>
__global__ __launch_bounds__(256, 2) void gemm_h16(
    const __half* __restrict__ XH, const __half* __restrict__ XL,
    const __half* __restrict__ WH, const __half* __restrict__ WL,
    const float* __restrict__ bias, int mode, float oscale,
    __half* __restrict__ YH, __half* __restrict__ YL, float* __restrict__ YF)
{
    extern __shared__ char sm[];
    const uint32_t smb = smem_u32(sm);

    const int t = threadIdx.x;
    const int w = t >> 5;
    const int lane = t & 31;
    const int g = lane >> 2;
    const int tig = lane & 3;
    const int warp_m = (w >> 2) * 64;
    const int warp_n = (w & 3) * 32;
    const int bm = blockIdx.y * 128;
    const int bn = blockIdx.x * 128;

    const int arow = lane & 15;
    const int acol = (lane >> 4) * 8;
    const int brow = (lane & 7) + ((lane >> 4) << 3);
    const int bcol = ((lane >> 3) & 1) * 8;

    const int r0c = t >> 2, c0c = t & 3;
    const int r1c = (t + 256) >> 2;

    float acc[4][4][4];
#pragma unroll
    for (int mi = 0; mi < 4; ++mi)
#pragma unroll
        for (int ni = 0; ni < 4; ++ni)
#pragma unroll
            for (int j = 0; j < 4; ++j) acc[mi][ni][j] = 0.0f;

    const int NS = GK / 32;

    auto issue = [&](int s, int buf) {
        const uint32_t bb = smb + buf * BUF_B;
        const size_t ks = (size_t)s * 32;
        CP_ASYNC16(bb + r0c * 80 + c0c * 16, XH + (size_t)(bm + r0c) * GK + ks + c0c * 8);
        CP_ASYNC16(bb + r1c * 80 + c0c * 16, XH + (size_t)(bm + r1c) * GK + ks + c0c * 8);
        if (NT == 3) {
            CP_ASYNC16(bb + MAT_B + r0c * 80 + c0c * 16, XL + (size_t)(bm + r0c) * GK + ks + c0c * 8);
            CP_ASYNC16(bb + MAT_B + r1c * 80 + c0c * 16, XL + (size_t)(bm + r1c) * GK + ks + c0c * 8);
        }
        CP_ASYNC16(bb + 2 * MAT_B + r0c * 80 + c0c * 16, WH + (size_t)(bn + r0c) * GK + ks + c0c * 8);
        CP_ASYNC16(bb + 2 * MAT_B + r1c * 80 + c0c * 16, WH + (size_t)(bn + r1c) * GK + ks + c0c * 8);
        if (NT >= 2) {
            CP_ASYNC16(bb + 3 * MAT_B + r0c * 80 + c0c * 16, WL + (size_t)(bn + r0c) * GK + ks + c0c * 8);
            CP_ASYNC16(bb + 3 * MAT_B + r1c * 80 + c0c * 16, WL + (size_t)(bn + r1c) * GK + ks + c0c * 8);
        }
    };

    issue(0, 0);
    CP_COMMIT();

    for (int s = 0; s < NS; ++s) {
        const int buf = s & 1;
        CP_WAIT0();
        __syncthreads();
        if (s + 1 < NS) {
            issue(s + 1, buf ^ 1);
            CP_COMMIT();
        }

        const uint32_t xb = smb + buf * BUF_B;
        const uint32_t wb = xb + 2 * MAT_B;

#pragma unroll
        for (int k16 = 0; k16 < 2; ++k16) {
            const int k0 = k16 * 16;
            uint32_t bh[4][2], bl[4][2];
#pragma unroll
            for (int p = 0; p < 2; ++p) {
                const uint32_t addr = wb + ((warp_n + p * 16 + brow) * LDH + k0 + bcol) * 2;
                ldsm_x4(bh[2*p][0], bh[2*p][1], bh[2*p+1][0], bh[2*p+1][1], addr);
                if (NT >= 2)
                    ldsm_x4(bl[2*p][0], bl[2*p][1], bl[2*p+1][0], bl[2*p+1][1], addr + MAT_B);
            }
#pragma unroll
            for (int mi = 0; mi < 4; ++mi) {
                const uint32_t addrA = xb + ((warp_m + mi * 16 + arow) * LDH + k0 + acol) * 2;
                uint32_t ah[4], al[4];
                ldsm_x4(ah[0], ah[1], ah[2], ah[3], addrA);
                if (NT == 3)
                    ldsm_x4(al[0], al[1], al[2], al[3], addrA + MAT_B);
#pragma unroll
                for (int ni = 0; ni < 4; ++ni) {
                    mma_f16(acc[mi][ni], ah[0], ah[1], ah[2], ah[3], bh[ni][0], bh[ni][1]);
                    if (NT >= 2)
                        mma_f16(acc[mi][ni], ah[0], ah[1], ah[2], ah[3], bl[ni][0], bl[ni][1]);
                    if (NT == 3)
                        mma_f16(acc[mi][ni], al[0], al[1], al[2], al[3], bh[ni][0], bh[ni][1]);
                }
            }
        }
        __syncthreads();
    }

    // ---- epilogue ----
#pragma unroll
    for (int ni = 0; ni < 4; ++ni) {
        const int n = bn + warp_n + ni * 8 + 2 * tig;
        const float2 b2 = *(const float2*)(bias + n);
#pragma unroll
        for (int mi = 0; mi < 4; ++mi) {
            const int r0 = bm + warp_m + mi * 16;
            float c0 = acc[mi][ni][0] + b2.x, c1 = acc[mi][ni][1] + b2.y;
            float c2 = acc[mi][ni][2] + b2.x, c3 = acc[mi][ni][3] + b2.y;
            if (mode == EP_F32) {
                *(float2*)(YF + (size_t)(r0 + g) * GN + n)     = make_float2(c0, c1);
                *(float2*)(YF + (size_t)(r0 + g + 8) * GN + n) = make_float2(c2, c3);
            } else if (mode == EP_H16) {
                c0 *= oscale; c1 *= oscale; c2 *= oscale; c3 *= oscale;
                __half2 h01, l01, h23, l23;
                split_h2(c0, c1, h01, l01);
                split_h2(c2, c3, h23, l23);
                *(__half2*)(YH + (size_t)(r0 + g) * GN + n)     = h01;
                *(__half2*)(YL + (size_t)(r0 + g) * GN + n)     = l01;
                *(__half2*)(YH + (size_t)(r0 + g + 8) * GN + n) = h23;
                *(__half2*)(YL + (size_t)(r0 + g + 8) * GN + n) = l23;
            } else {   // EP_VT: hi only
                __half2 h01 = __floats2half2_rn(c0, c1);
                __half2 h23 = __floats2half2_rn(c2, c3);
                const int m0r = r0 + g, m1r = r0 + g + 8;
                const size_t a00 = ((size_t)((m0r >> 11) * 1024 + n))     * 2048 + (m0r & 2047);
                const size_t a01 = ((size_t)((m0r >> 11) * 1024 + n + 1)) * 2048 + (m0r & 2047);
                const size_t a10 = ((size_t)((m1r >> 11) * 1024 + n))     * 2048 + (m1r & 2047);
                const size_t a11 = ((size_t)((m1r >> 11) * 1024 + n + 1)) * 2048 + (m1r & 2047);
                YH[a00] = __low2half(h01);
                YH[a01] = __high2half(h01);
                YH[a10] = __low2half(h23);
                YH[a11] = __high2half(h23);
            }
        }
    }
}

// ---------------- persistent fused flash attention -----------------------------
#define ALD 88
#define ABUF 33792
#define AT_SMEM 86032
#define NUNITS 512

__global__ __launch_bounds__(256, 2) void attn_fused(float* __restrict__ atp) {
    extern __shared__ char sm[];
    const uint32_t smb = smem_u32(sm);
    float* mhist = (float*)(sm + 67584);
    float* red   = (float*)(sm + 83968);
    int* s_unit  = (int*)(sm + 86016);

    const int t = threadIdx.x;
    const int w = t >> 5;
    const int lane = t & 31;
    const int g = lane >> 2;
    const int tig = lane & 3;

    const int brow = (lane & 7) + ((lane >> 4) << 3);
    const int bcol = ((lane >> 3) & 1) * 8;

    const int r0c = t >> 3, c0c = t & 7;
    const int r1c = (t + 256) >> 3;

    while (true) {
        if (t == 0) *s_unit = atomicAdd(&g_ctr, 1);
        __syncthreads();
        const int u = *s_unit;
        if (u >= NUNITS) break;

        const int bh = u >> 4;
        const int qt = u & 15;
        const int b = bh >> 4, h = bh & 15;
        const int q0 = qt * 128;
        const int blk = u;

        // ---- Q fragments (pre-scaled by 12.5) ----
        uint32_t qh[4][4], ql[4][4];
        {
            const size_t rowA = (size_t)(b * SS + q0 + 16 * w + g) * DD + h * DK;
            const size_t rowB = (size_t)(b * SS + q0 + 16 * w + g + 8) * DD + h * DK;
#pragma unroll
            for (int j = 0; j < 4; ++j) {
                qh[j][0] = *(const uint32_t*)&g_QH[rowA + 16 * j + 2 * tig];
                qh[j][1] = *(const uint32_t*)&g_QH[rowB + 16 * j + 2 * tig];
                qh[j][2] = *(const uint32_t*)&g_QH[rowA + 16 * j + 8 + 2 * tig];
                qh[j][3] = *(const uint32_t*)&g_QH[rowB + 16 * j + 8 + 2 * tig];
                ql[j][0] = *(const uint32_t*)&g_QL[rowA + 16 * j + 2 * tig];
                ql[j][1] = *(const uint32_t*)&g_QL[rowB + 16 * j + 2 * tig];
                ql[j][2] = *(const uint32_t*)&g_QL[rowA + 16 * j + 8 + 2 * tig];
                ql[j][3] = *(const uint32_t*)&g_QL[rowB + 16 * j + 8 + 2 * tig];
            }
        }

        auto issueT = [&](int tile, int buf) {
            const uint32_t bb = smb + buf * ABUF;
            const size_t ksrc0 = (size_t)(b * SS + tile * 64 + r0c) * DD + h * DK + c0c * 8;
            const size_t ksrc1 = (size_t)(b * SS + tile * 64 + r1c) * DD + h * DK + c0c * 8;
            const size_t vsrc0 = (size_t)(b * 1024 + h * 64 + r0c) * 2048 + tile * 64 + c0c * 8;
            const size_t vsrc1 = (size_t)(b * 1024 + h * 64 + r1c) * 2048 + tile * 64 + c0c * 8;
            const uint32_t d0 = r0c * 176 + c0c * 16;
            const uint32_t d1 = r1c * 176 + c0c * 16;
            CP_ASYNC16(bb + d0,         g_KH + ksrc0);
            CP_ASYNC16(bb + d1,         g_KH + ksrc1);
            CP_ASYNC16(bb + 11264 + d0, g_KL + ksrc0);
            CP_ASYNC16(bb + 11264 + d1, g_KL + ksrc1);
            CP_ASYNC16(bb + 22528 + d0, g_VtH + vsrc0);
            CP_ASYNC16(bb + 22528 + d1, g_VtH + vsrc1);
        };

        float oacc[8][4];
#pragma unroll
        for (int ni = 0; ni < 8; ++ni)
#pragma unroll
            for (int j = 0; j < 4; ++j) oacc[ni][j] = 0.0f;

        float m0 = -INFINITY, m1 = -INFINITY, l0 = 0.0f, l1 = 0.0f;

        issueT(0, 0);
        CP_COMMIT();

        for (int tile = 0; tile < 32; ++tile) {
            const int buf = tile & 1;
            CP_WAIT0();
            __syncthreads();
            if (tile + 1 < 32) {
                issueT(tile + 1, buf ^ 1);
                CP_COMMIT();
            }
            const uint32_t bb = smb + buf * ABUF;

            // ---- QK^T (3-term, exact) ----
            float sacc[8][4];
#pragma unroll
            for (int ni = 0; ni < 8; ++ni)
#pragma unroll
                for (int j = 0; j < 4; ++j) sacc[ni][j] = 0.0f;

#pragma unroll
            for (int j = 0; j < 4; ++j) {
                const int k0 = 16 * j;
#pragma unroll
                for (int p = 0; p < 4; ++p) {
                    const uint32_t addr = bb + ((p * 16 + brow) * ALD + k0 + bcol) * 2;
                    uint32_t b0, b1, b2, b3, c0, c1, c2, c3;
                    ldsm_x4(b0, b1, b2, b3, addr);
                    ldsm_x4(c0, c1, c2, c3, addr + 11264);
                    mma_f16(sacc[2*p],   qh[j][0], qh[j][1], qh[j][2], qh[j][3], b0, b1);
                    mma_f16(sacc[2*p],   qh[j][0], qh[j][1], qh[j][2], qh[j][3], c0, c1);
                    mma_f16(sacc[2*p],   ql[j][0], ql[j][1], ql[j][2], ql[j][3], b0, b1);
                    mma_f16(sacc[2*p+1], qh[j][0], qh[j][1], qh[j][2], qh[j][3], b2, b3);
                    mma_f16(sacc[2*p+1], qh[j][0], qh[j][1], qh[j][2], qh[j][3], c2, c3);
                    mma_f16(sacc[2*p+1], ql[j][0], ql[j][1], ql[j][2], ql[j][3], b2, b3);
                }
            }

            // ---- row max ----
            float mx0 = -INFINITY, mx1 = -INFINITY;
#pragma unroll
            for (int ni = 0; ni < 8; ++ni) {
                mx0 = fmaxf(mx0, fmaxf(sacc[ni][0], sacc[ni][1]));
                mx1 = fmaxf(mx1, fmaxf(sacc[ni][2], sacc[ni][3]));
            }
            mx0 = fmaxf(mx0, __shfl_xor_sync(0xffffffffu, mx0, 1));
            mx0 = fmaxf(mx0, __shfl_xor_sync(0xffffffffu, mx0, 2));
            mx1 = fmaxf(mx1, __shfl_xor_sync(0xffffffffu, mx1, 1));
            mx1 = fmaxf(mx1, __shfl_xor_sync(0xffffffffu, mx1, 2));

            const float mn0 = fmaxf(m0, mx0);
            const float mn1 = fmaxf(m1, mx1);
            const float al0 = __expf(m0 - mn0);
            const float al1 = __expf(m1 - mn1);
            m0 = mn0; m1 = mn1;

            // ---- u = exp(s-m); fp16 packs for PV; e4m3 to scratch ----
            float ls0 = 0.0f, ls1 = 0.0f;
            uint32_t uf[8][2];
            uint32_t u8[8];
#pragma unroll
            for (int ni = 0; ni < 8; ++ni) {
                float u0 = __expf(sacc[ni][0] - m0);
                float u1 = __expf(sacc[ni][1] - m0);
                float u2 = __expf(sacc[ni][2] - m1);
                float u3 = __expf(sacc[ni][3] - m1);
                ls0 += u0 + u1; ls1 += u2 + u3;
                __half2 p01 = __floats2half2_rn(u0, u1);
                __half2 p23 = __floats2half2_rn(u2, u3);
                uf[ni][0] = *(uint32_t*)&p01;
                uf[ni][1] = *(uint32_t*)&p23;
                u8[ni] = pack4_e4m3(u0, u1, u2, u3);
            }
            {
                uint4* U4 = (uint4*)g_U + ((size_t)(blk * 32 + tile) * 2) * 256 + t;
                U4[0]   = make_uint4(u8[0], u8[1], u8[2], u8[3]);
                U4[256] = make_uint4(u8[4], u8[5], u8[6], u8[7]);
            }
            l0 = l0 * al0 + ls0;
            l1 = l1 * al1 + ls1;

            if (tig == 0) {
                mhist[tile * 128 + 16 * w + g]     = m0;
                mhist[tile * 128 + 16 * w + g + 8] = m1;
            }

#pragma unroll
            for (int ni = 0; ni < 8; ++ni) {
                oacc[ni][0] *= al0; oacc[ni][1] *= al0;
                oacc[ni][2] *= al1; oacc[ni][3] *= al1;
            }

            // ---- PV: pure fp16 ----
#pragma unroll
            for (int j = 0; j < 4; ++j) {
                const uint32_t a0 = uf[2*j][0],   a1 = uf[2*j][1];
                const uint32_t a2 = uf[2*j+1][0], a3 = uf[2*j+1][1];
                const int k0 = 16 * j;
#pragma unroll
                for (int p = 0; p < 4; ++p) {
                    const uint32_t addr = bb + 22528 + ((p * 16 + brow) * ALD + k0 + bcol) * 2;
                    uint32_t b0, b1, b2, b3;
                    ldsm_x4(b0, b1, b2, b3, addr);
                    mma_f16(oacc[2*p],   a0, a1, a2, a3, b0, b1);
                    mma_f16(oacc[2*p+1], a0, a1, a2, a3, b2, b3);
                }
            }
            __syncthreads();
        }

        // ---- finalize ----
        l0 += __shfl_xor_sync(0xffffffffu, l0, 1);
        l0 += __shfl_xor_sync(0xffffffffu, l0, 2);
        l1 += __shfl_xor_sync(0xffffffffu, l1, 1);
        l1 += __shfl_xor_sync(0xffffffffu, l1, 2);
        const float il0 = 1.0f / l0;
        const float il1 = 1.0f / l1;

        {
            const size_t rowA = (size_t)(b * SS + q0 + 16 * w + g) * DD + h * DK;
            const size_t rowB = (size_t)(b * SS + q0 + 16 * w + g + 8) * DD + h * DK;
#pragma unroll
            for (int ni = 0; ni < 8; ++ni) {
                const int col = ni * 8 + 2 * tig;
                *(__half2*)&g_CH[rowA + col] =
                    __floats2half2_rn(oacc[ni][0] * il0, oacc[ni][1] * il0);
                *(__half2*)&g_CH[rowB + col] =
                    __floats2half2_rn(oacc[ni][2] * il1, oacc[ni][3] * il1);
            }
        }

        __syncthreads();

        // ---- colsum readback (e4m3) ----
        for (int tile = 0; tile < 32; ++tile) {
            const uint4* U4 = (const uint4*)g_U + ((size_t)(blk * 32 + tile) * 2) * 256 + t;
            uint32_t uu[8];
            *(uint4*)&uu[0] = U4[0];
            *(uint4*)&uu[4] = U4[256];
            const float w0 = __expf(mhist[tile * 128 + 16 * w + g]     - m0) * il0;
            const float w1 = __expf(mhist[tile * 128 + 16 * w + g + 8] - m1) * il1;

#pragma unroll
            for (int ni = 0; ni < 8; ++ni) {
                float2 fa = unpack2_e4m3((uint16_t)(uu[ni] & 0xFFFF));
                float2 fb = unpack2_e4m3((uint16_t)(uu[ni] >> 16));
                float cs0 = fa.x * w0 + fb.x * w1;
                float cs1 = fa.y * w0 + fb.y * w1;
                cs0 += __shfl_xor_sync(0xffffffffu, cs0, 4);
                cs0 += __shfl_xor_sync(0xffffffffu, cs0, 8);
                cs0 += __shfl_xor_sync(0xffffffffu, cs0, 16);
                cs1 += __shfl_xor_sync(0xffffffffu, cs1, 4);
                cs1 += __shfl_xor_sync(0xffffffffu, cs1, 8);
                cs1 += __shfl_xor_sync(0xffffffffu, cs1, 16);
                if (lane < 4) {
                    red[w * 64 + ni * 8 + 2 * tig]     = cs0;
                    red[w * 64 + ni * 8 + 2 * tig + 1] = cs1;
                }
            }
            __syncthreads();
            if (t < 64) {
                float s = 0.0f;
#pragma unroll
                for (int wi = 0; wi < 8; ++wi) s += red[wi * 64 + t];
                atomicAdd(&atp[b * SS + tile * 64 + t], s * INV_HS);
            }
            __syncthreads();
        }
    }
}

// ---------------- launch ------------------------------------------------------
extern "C" void kernel_launch(void* const* d_in, const int* in_sizes, int n_in,
                              void* d_out, int out_size) {
    (void)in_sizes; (void)n_in; (void)out_size;
    const float* query = (const float*)d_in[0];
    const float* key   = (const float*)d_in[1];
    const float* value = (const float*)d_in[2];
    const float* Wq = (const float*)d_in[3];
    const float* bq = (const float*)d_in[4];
    const float* Wk = (const float*)d_in[5];
    const float* bk = (const float*)d_in[6];
    const float* Wv = (const float*)d_in[7];
    const float* bv = (const float*)d_in[8];
    const float* Wo = (const float*)d_in[9];
    const float* bo = (const float*)d_in[10];

    float* out = (float*)d_out;
    float* atp = out + (size_t)BB * SS * DD;

    __half *inH, *inL, *QH, *QL, *KH, *KL, *VtH, *CH;
    cudaGetSymbolAddress((void**)&inH, g_inH);
    cudaGetSymbolAddress((void**)&inL, g_inL);
    cudaGetSymbolAddress((void**)&QH, g_QH);
    cudaGetSymbolAddress((void**)&QL, g_QL);
    cudaGetSymbolAddress((void**)&KH, g_KH);
    cudaGetSymbolAddress((void**)&KL, g_KL);
    cudaGetSymbolAddress((void**)&VtH, g_VtH);
    cudaGetSymbolAddress((void**)&CH, g_CH);

    zero_atp_kernel<<<(BB*SS + 255) / 256, 256>>>(atp);

    const int NX4 = MTOT * DD / 4;          // 1048576
    const int NW4 = DD * DD / 4;            // 262144
    const size_t oWq = 12582912;
    split_in3<<<dim3(NX4 / 256, 3), 256>>>(query, key, value, inH, inL, NX4);
    split_w4<<<dim3(NW4 / 256, 4), 256>>>(Wq, Wk, Wv, Wo, inH + oWq, inL + oWq, NW4);

    cudaFuncSetAttribute(gemm_h16<3>, cudaFuncAttributeMaxDynamicSharedMemorySize,
                         GEMM_SMEM);
    cudaFuncSetAttribute(gemm_h16<1>, cudaFuncAttributeMaxDynamicSharedMemorySize,
                         GEMM_SMEM);
    cudaFuncSetAttribute(attn_fused, cudaFuncAttributeMaxDynamicSharedMemorySize,
                         AT_SMEM);

    const size_t oQ = 0, oK = 4194304, oV = 8388608;
    const size_t oWk = 13631488, oWv = 14680064, oWo = 15728640;
    dim3 gg(GN / 128, MTOT / 128);
    gemm_h16<3><<<gg, 256, GEMM_SMEM>>>(inH + oQ, inL + oQ, inH + oWq, inL + oWq,
                                        bq, EP_H16, SCALE, QH, QL, nullptr);
    gemm_h16<3><<<gg, 256, GEMM_SMEM>>>(inH + oK, inL + oK, inH + oWk, inL + oWk,
                                        bk, EP_H16, 1.0f, KH, KL, nullptr);
    gemm_h16<1><<<gg, 256, GEMM_SMEM>>>(inH + oV, nullptr, inH + oWv, nullptr,
                                        bv, EP_VT, 1.0f, VtH, nullptr, nullptr);

    attn_fused<<<296, 256, AT_SMEM>>>(atp);

    gemm_h16<1><<<gg, 256, GEMM_SMEM>>>(CH, nullptr, inH + oWo, nullptr,
                                        bo, EP_F32, 1.0f, nullptr, nullptr, out);
}